// round 14
// baseline (speedup 1.0000x reference)
#include <cuda_runtime.h>
#include <cuda_bf16.h>
#include <cstdint>

#define N_NODES 20000
#define E_EDGES 640000
#define IN_DIM  24
#define H       128
#define OUT_DIM 24
#define MAPD    512

typedef unsigned long long u64;

// ---------------- mma / ldmatrix helpers (baseline PTX, compute_103-safe) ----------------
__device__ __forceinline__ unsigned smem_u32(const void* p) {
    unsigned r;
    asm("{.reg .u64 t; cvta.to.shared.u64 t, %1; cvt.u32.u64 %0, t;}" : "=r"(r) : "l"(p));
    return r;
}
__device__ __forceinline__ void ldsm_x4(unsigned* r, unsigned addr) {
    asm volatile("ldmatrix.sync.aligned.m8n8.x4.shared.b16 {%0,%1,%2,%3}, [%4];"
                 : "=r"(r[0]), "=r"(r[1]), "=r"(r[2]), "=r"(r[3]) : "r"(addr));
}
__device__ __forceinline__ void mma16816(float* c, const unsigned* a, unsigned b0, unsigned b1) {
    asm volatile(
        "mma.sync.aligned.m16n8k16.row.col.f32.bf16.bf16.f32 "
        "{%0,%1,%2,%3}, {%4,%5,%6,%7}, {%8,%9}, {%0,%1,%2,%3};"
        : "+f"(c[0]), "+f"(c[1]), "+f"(c[2]), "+f"(c[3])
        : "r"(a[0]), "r"(a[1]), "r"(a[2]), "r"(a[3]), "r"(b0), "r"(b1));
}
__device__ __forceinline__ unsigned pack_bf2(float x, float y) {
    __nv_bfloat162 t = __floats2bfloat162_rn(x, y);
    return *(unsigned*)&t;
}

// ---------------- scratch ----------------
__device__ float g_hemb[N_NODES * H];
__device__ float g_hA[N_NODES * H];
__device__ float g_hB[N_NODES * H];
__device__ float g_hs[N_NODES * H];
__device__ float g_z[N_NODES * H];
__device__ float g_ssrc[N_NODES];
__device__ float g_sdst[N_NODES];
__device__ int   g_offs[N_NODES + 1];
__device__ int   g_cnt[N_NODES];
__device__ int   g_cur[N_NODES];
__device__ int   g_csrc[E_EDGES];
// pre-split weights: [Wcat 81920][Ws1 16384][Wf1 16384][Ws2 16384][Wf2 16384]
#define W_TOT (81920 + 4 * 16384)
__device__ __nv_bfloat16 g_Wh[W_TOT];
__device__ __nv_bfloat16 g_Wl[W_TOT];

// ---------------- CSR build ----------------
__global__ void k_zero() {
    int i = blockIdx.x * blockDim.x + threadIdx.x;
    if (i < N_NODES) { g_cnt[i] = 0; g_cur[i] = 0; }
}

__global__ void k_hist_embed(const int* __restrict__ dst,
                             const float* __restrict__ feats,
                             const float* __restrict__ W_eh,
                             const float* __restrict__ b_eh) {
    if (blockIdx.x < 2500) {
        int e = blockIdx.x * 256 + threadIdx.x;
        if (e < E_EDGES) atomicAdd(&g_cnt[dst[e]], 1);
        return;
    }
    int nb = blockIdx.x - 2500;
    __shared__ float f[2][IN_DIM];
    int half = threadIdx.x >> 7;
    int h = threadIdx.x & 127;
    int n = nb * 2 + half;
    if (h < IN_DIM) f[half][h] = feats[n * IN_DIM + h];
    __syncthreads();
    float acc = b_eh[h];
    #pragma unroll
    for (int k = 0; k < IN_DIM; k++) acc += f[half][k] * W_eh[h * IN_DIM + k];
    g_hemb[n * H + h] = acc;
}

__global__ void k_scan() {
    const int PER = 20;
    int t = threadIdx.x;
    int base = t * PER;
    int vals[PER];
    int s = 0;
    #pragma unroll
    for (int p = 0; p < PER; p++) {
        int i = base + p;
        int v = (i < N_NODES) ? g_cnt[i] : 0;
        vals[p] = s;
        s += v;
    }
    __shared__ int sh[1024];
    sh[t] = s;
    __syncthreads();
    #pragma unroll
    for (int off = 1; off < 1024; off <<= 1) {
        int x = (t >= off) ? sh[t - off] : 0;
        __syncthreads();
        sh[t] += x;
        __syncthreads();
    }
    int excl = sh[t] - s;
    #pragma unroll
    for (int p = 0; p < PER; p++) {
        int i = base + p;
        if (i < N_NODES) g_offs[i] = excl + vals[p];
    }
    if (t == 1023) g_offs[N_NODES] = sh[1023];
}

__global__ void k_scatter(const int* __restrict__ src, const int* __restrict__ dst) {
    int e = blockIdx.x * blockDim.x + threadIdx.x;
    if (e < E_EDGES) {
        int d = dst[e];
        int p = g_offs[d] + atomicAdd(&g_cur[d], 1);
        g_csrc[p] = src[e];
    }
}

// ---------------- weight split prep ----------------
__global__ void k_wsplit(const float* __restrict__ Wcat, const float* __restrict__ Ws1,
                         const float* __restrict__ Wf1, const float* __restrict__ Ws2,
                         const float* __restrict__ Wf2) {
    int i = blockIdx.x * 256 + threadIdx.x;
    if (i >= W_TOT) return;
    float v;
    if (i < 81920) v = Wcat[i];
    else {
        int j = i - 81920;
        int m = j >> 14, o = j & 16383;
        v = (m == 0 ? Ws1 : (m == 1 ? Wf1 : (m == 2 ? Ws2 : Wf2)))[o];
    }
    __nv_bfloat16 h = __float2bfloat16(v);
    __nv_bfloat16 l = __float2bfloat16(v - __bfloat162float(h));
    g_Wh[i] = h;
    g_Wl[i] = l;
}

// ---------------- HMMA bf16x3-split GEMM ----------------
// C[row0:row0+128, 0:128] = X @ W[128,KDIM]^T (+bias+relu)
// 8 warps: wm = wid&3 (32 rows), wn = wid>>2 (64 cols)
// smem: AH/AL [128][64] bf16 (16KB each), BH/BL [128][64] bf16 (16KB each) = 64KB
template <int KDIM, bool CONCAT, bool BIASRELU, bool DUAL>
__global__ void __launch_bounds__(256)
k_mma(const float* __restrict__ A0, const float* __restrict__ A1,
      const __nv_bfloat16* __restrict__ WhB, const __nv_bfloat16* __restrict__ WlB,
      const float* __restrict__ bias,
      float* __restrict__ C0, float* __restrict__ C1) {
    extern __shared__ char sm[];
    const unsigned OFF_AH = 0, OFF_AL = 16384, OFF_BH = 32768, OFF_BL = 49152;
    unsigned sb = smem_u32(sm);

    int tid = threadIdx.x, lane = tid & 31, wid = tid >> 5;
    int wm = wid & 3, wn = wid >> 2;
    int y = DUAL ? blockIdx.y : 0;
    const __nv_bfloat16* Wh = WhB + (DUAL ? y * (128 * KDIM) : 0);
    const __nv_bfloat16* Wl = WlB + (DUAL ? y * (128 * KDIM) : 0);
    float* C = DUAL ? (y ? C1 : C0) : C0;
    int row0 = blockIdx.x * 128;

    float acc[2][8][4];
    #pragma unroll
    for (int i = 0; i < 2; i++)
        #pragma unroll
        for (int j = 0; j < 8; j++)
            #pragma unroll
            for (int q = 0; q < 4; q++) acc[i][j][q] = 0.f;

    // ldmatrix address precompute
    // A: matrix layout: khalf = lane>>4, rowhalf = (lane>>3)&1, r8 = lane&7
    int a_rh = (lane >> 3) & 1, a_kh = lane >> 4, r8 = lane & 7;
    int rowA[2], xorA[2];
    #pragma unroll
    for (int mt = 0; mt < 2; mt++) {
        rowA[mt] = wm * 32 + mt * 16 + a_rh * 8 + r8;
        xorA[mt] = rowA[mt] & 7;
    }
    // B: nhalf = (lane>>4)&1, khalf = (lane>>3)&1
    int b_nh = (lane >> 4) & 1, b_kh = (lane >> 3) & 1;
    int rowB[4], xorB[4];
    #pragma unroll
    for (int nt2 = 0; nt2 < 4; nt2++) {
        rowB[nt2] = wn * 64 + nt2 * 16 + b_nh * 8 + r8;
        xorB[nt2] = rowB[nt2] & 7;
    }

    const int NT = KDIM / 64;
    for (int kt = 0; kt < NT; kt++) {
        int k0 = kt * 64;
        // --- A tile: 128x64 fp32 -> hi/lo bf16, swizzled ---
        #pragma unroll
        for (int p = 0; p < 8; p++) {
            int idx = tid + p * 256;
            int row = idx >> 4, c4 = idx & 15;
            int grow = row0 + row, gk = k0 + c4 * 4;
            float4 v = make_float4(0.f, 0.f, 0.f, 0.f);
            if (grow < N_NODES) {
                if (CONCAT) v = (gk < MAPD) ? *(const float4*)&A0[grow * MAPD + gk]
                                            : *(const float4*)&A1[grow * H + (gk - MAPD)];
                else        v = *(const float4*)&A0[grow * KDIM + gk];
            }
            unsigned h0 = pack_bf2(v.x, v.y), h1 = pack_bf2(v.z, v.w);
            float rx = v.x - __bfloat162float(__float2bfloat16(v.x));
            float ry = v.y - __bfloat162float(__float2bfloat16(v.y));
            float rz = v.z - __bfloat162float(__float2bfloat16(v.z));
            float rw = v.w - __bfloat162float(__float2bfloat16(v.w));
            unsigned l0 = pack_bf2(rx, ry), l1 = pack_bf2(rz, rw);
            unsigned off = row * 128 + c4 * 8;
            unsigned sw = off ^ ((row & 7) << 4);
            *(uint2*)(sm + OFF_AH + sw) = make_uint2(h0, h1);
            *(uint2*)(sm + OFF_AL + sw) = make_uint2(l0, l1);
        }
        // --- B tile: 128x64 bf16 hi/lo (pre-split), swizzled ---
        #pragma unroll
        for (int p = 0; p < 4; p++) {
            int idx = tid + p * 256;
            int row = idx >> 3, c16 = idx & 7;
            unsigned off = row * 128 + c16 * 16;
            unsigned sw = off ^ ((row & 7) << 4);
            const __nv_bfloat16* gh = &Wh[row * KDIM + k0 + c16 * 8];
            const __nv_bfloat16* gl = &Wl[row * KDIM + k0 + c16 * 8];
            *(uint4*)(sm + OFF_BH + sw) = *(const uint4*)gh;
            *(uint4*)(sm + OFF_BL + sw) = *(const uint4*)gl;
        }
        __syncthreads();

        #pragma unroll
        for (int ks = 0; ks < 4; ks++) {
            unsigned ah[2][4], al[2][4];
            #pragma unroll
            for (int mt = 0; mt < 2; mt++) {
                unsigned chunk = (ks * 2 + a_kh) ^ xorA[mt];
                unsigned o = rowA[mt] * 128 + chunk * 16;
                ldsm_x4(ah[mt], sb + OFF_AH + o);
                ldsm_x4(al[mt], sb + OFF_AL + o);
            }
            unsigned bh[4][4], bl[4][4];
            #pragma unroll
            for (int nt2 = 0; nt2 < 4; nt2++) {
                unsigned chunk = (ks * 2 + b_kh) ^ xorB[nt2];
                unsigned o = rowB[nt2] * 128 + chunk * 16;
                ldsm_x4(bh[nt2], sb + OFF_BH + o);
                ldsm_x4(bl[nt2], sb + OFF_BL + o);
            }
            #pragma unroll
            for (int mt = 0; mt < 2; mt++)
                #pragma unroll
                for (int nt = 0; nt < 8; nt++) {
                    float* c = acc[mt][nt];
                    unsigned s = (nt & 1) * 2;
                    const unsigned* BH_ = bh[nt >> 1];
                    const unsigned* BL_ = bl[nt >> 1];
                    mma16816(c, ah[mt], BH_[s], BH_[s + 1]);
                    mma16816(c, ah[mt], BL_[s], BL_[s + 1]);
                    mma16816(c, al[mt], BH_[s], BH_[s + 1]);
                }
        }
        __syncthreads();
    }

    // --- epilogue ---
    int cbase = wn * 64 + (lane & 3) * 2;
    int rbase = row0 + wm * 32 + (lane >> 2);
    #pragma unroll
    for (int mt = 0; mt < 2; mt++) {
        #pragma unroll
        for (int nt = 0; nt < 8; nt++) {
            int col = cbase + nt * 8;
            float b0 = 0.f, b1 = 0.f;
            if (BIASRELU) { b0 = bias[col]; b1 = bias[col + 1]; }
            int r0 = rbase + mt * 16;
            int r1 = r0 + 8;
            float* c = acc[mt][nt];
            if (r0 < N_NODES) {
                float2 v = make_float2(c[0] + b0, c[1] + b1);
                if (BIASRELU) { v.x = fmaxf(v.x, 0.f); v.y = fmaxf(v.y, 0.f); }
                *(float2*)&C[r0 * H + col] = v;
            }
            if (r1 < N_NODES) {
                float2 v = make_float2(c[2] + b0, c[3] + b1);
                if (BIASRELU) { v.x = fmaxf(v.x, 0.f); v.y = fmaxf(v.y, 0.f); }
                *(float2*)&C[r1 * H + col] = v;
            }
        }
    }
}
#define MMA_SMEM 65536

// ---------------- per-node attention halves ----------------
__global__ void k_sdot(const float* __restrict__ a) {
    int warp = (blockIdx.x * blockDim.x + threadIdx.x) >> 5;
    int lane = threadIdx.x & 31;
    if (warp >= N_NODES) return;
    float4 zv = *(const float4*)&g_z[warp * H + lane * 4];
    float4 a0 = *(const float4*)&a[lane * 4];
    float4 a1 = *(const float4*)&a[H + lane * 4];
    float s0 = zv.x * a0.x + zv.y * a0.y + zv.z * a0.z + zv.w * a0.w;
    float s1 = zv.x * a1.x + zv.y * a1.y + zv.z * a1.z + zv.w * a1.w;
    #pragma unroll
    for (int off = 16; off; off >>= 1) {
        s0 += __shfl_xor_sync(0xffffffffu, s0, off);
        s1 += __shfl_xor_sync(0xffffffffu, s1, off);
    }
    if (lane == 0) { g_ssrc[warp] = s0; g_sdst[warp] = s1; }
}

// ---------------- fused GAT edge kernel (warp/node); optional out-proj epilogue ----------------
template <bool DO_OUT>
__global__ void k_gat(const float* __restrict__ hin, float* __restrict__ hout,
                      const float* __restrict__ Wout, const float* __restrict__ bout,
                      float* __restrict__ out) {
    __shared__ float ws[DO_OUT ? OUT_DIM * H : 1];
    __shared__ float bs[DO_OUT ? OUT_DIM : 1];
    if (DO_OUT) {
        for (int i = threadIdx.x; i < OUT_DIM * H; i += blockDim.x) ws[i] = Wout[i];
        if (threadIdx.x < OUT_DIM) bs[threadIdx.x] = bout[threadIdx.x];
        __syncthreads();
    }
    int node = blockIdx.x * (blockDim.x >> 5) + (threadIdx.x >> 5);
    int lane = threadIdx.x & 31;
    if (node >= N_NODES) return;
    int beg = g_offs[node], end = g_offs[node + 1];
    float4 hi = *(const float4*)&hin[node * H + lane * 4];
    float4 o4;
    if (beg == end) {
        o4 = make_float4(2.f * hi.x, 2.f * hi.y, 2.f * hi.z, 2.f * hi.w);
    } else {
        float sd = g_sdst[node];
        float mx = -3.0e38f;
        for (int j = beg + lane; j < end; j += 32) {
            float x = g_ssrc[g_csrc[j]] + sd;
            mx = fmaxf(mx, fmaxf(x, 0.01f * x));
        }
        #pragma unroll
        for (int off = 16; off; off >>= 1) mx = fmaxf(mx, __shfl_xor_sync(0xffffffffu, mx, off));
        float den = 0.f;
        for (int j = beg + lane; j < end; j += 32) {
            float x = g_ssrc[g_csrc[j]] + sd;
            den += __expf(fmaxf(x, 0.01f * x) - mx);
        }
        #pragma unroll
        for (int off = 16; off; off >>= 1) den += __shfl_xor_sync(0xffffffffu, den, off);
        float invden = 1.f / fmaxf(den, 1e-16f);
        float4 acc = make_float4(0.f, 0.f, 0.f, 0.f);
        for (int base = beg; base < end; base += 32) {
            int j = base + lane;
            float coeff = 0.f; int s = 0;
            if (j < end) {
                s = g_csrc[j];
                float x = g_ssrc[s] + sd;
                coeff = __expf(fmaxf(x, 0.01f * x) - mx) * invden;
            }
            int cnt = min(32, end - base);
            if (cnt == 32) {
                #pragma unroll 8
                for (int t = 0; t < 32; t++) {
                    float c = __shfl_sync(0xffffffffu, coeff, t);
                    int ss = __shfl_sync(0xffffffffu, s, t);
                    float4 zv = *(const float4*)&g_z[ss * H + lane * 4];
                    acc.x += c * zv.x; acc.y += c * zv.y;
                    acc.z += c * zv.z; acc.w += c * zv.w;
                }
            } else {
                for (int t = 0; t < cnt; t++) {
                    float c = __shfl_sync(0xffffffffu, coeff, t);
                    int ss = __shfl_sync(0xffffffffu, s, t);
                    float4 zv = *(const float4*)&g_z[ss * H + lane * 4];
                    acc.x += c * zv.x; acc.y += c * zv.y;
                    acc.z += c * zv.z; acc.w += c * zv.w;
                }
            }
        }
        float4 hs = *(const float4*)&g_hs[node * H + lane * 4];
        o4 = make_float4(hi.x + hs.x + acc.x, hi.y + hs.y + acc.y,
                         hi.z + hs.z + acc.z, hi.w + hs.w + acc.w);
    }
    if (!DO_OUT) {
        *(float4*)&hout[node * H + lane * 4] = o4;
    } else {
        float vout = 0.f;
        #pragma unroll
        for (int o = 0; o < OUT_DIM; o++) {
            float4 wv = *(const float4*)&ws[o * H + lane * 4];
            float p = o4.x * wv.x + o4.y * wv.y + o4.z * wv.z + o4.w * wv.w;
            #pragma unroll
            for (int off = 16; off; off >>= 1) p += __shfl_xor_sync(0xffffffffu, p, off);
            if (lane == o) vout = p + bs[o];
        }
        if (lane < OUT_DIM) out[node * OUT_DIM + lane] = vout;
    }
}

// ---------------- launch ----------------
extern "C" void kernel_launch(void* const* d_in, const int* in_sizes, int n_in,
                              void* d_out, int out_size) {
    const float* feats = (const float*)d_in[0];
    const float* maps  = (const float*)d_in[2];
    const int*   src   = (const int*)d_in[4];
    const int*   dst   = (const int*)d_in[5];
    const float* W_eh  = (const float*)d_in[6];
    const float* b_eh  = (const float*)d_in[7];
    const float* W_cat = (const float*)d_in[10];
    const float* b_cat = (const float*)d_in[11];
    const float* Ws1   = (const float*)d_in[12];
    const float* Wf1   = (const float*)d_in[13];
    const float* a1    = (const float*)d_in[14];
    const float* Ws2   = (const float*)d_in[15];
    const float* Wf2   = (const float*)d_in[16];
    const float* a2    = (const float*)d_in[17];
    const float* W_out = (const float*)d_in[18];
    const float* b_out = (const float*)d_in[19];
    float* out = (float*)d_out;

    float *hemb, *hA, *hB, *hs, *z;
    cudaGetSymbolAddress((void**)&hemb, g_hemb);
    cudaGetSymbolAddress((void**)&hA, g_hA);
    cudaGetSymbolAddress((void**)&hB, g_hB);
    cudaGetSymbolAddress((void**)&hs, g_hs);
    cudaGetSymbolAddress((void**)&z,  g_z);
    __nv_bfloat16 *wh, *wl;
    cudaGetSymbolAddress((void**)&wh, g_Wh);
    cudaGetSymbolAddress((void**)&wl, g_Wl);

    cudaFuncSetAttribute(k_mma<MAPD + H, true, true, false>,
                         cudaFuncAttributeMaxDynamicSharedMemorySize, MMA_SMEM);
    cudaFuncSetAttribute(k_mma<H, false, false, true>,
                         cudaFuncAttributeMaxDynamicSharedMemorySize, MMA_SMEM);

    const int MB = (N_NODES + 127) / 128; // 157
    const int EB = (E_EDGES + 255) / 256; // 2500
    const int WB = (N_NODES + 7) / 8;     // 2500

    k_zero<<<(N_NODES + 255) / 256, 256>>>();                      // 0
    k_hist_embed<<<EB + 10000, 256>>>(dst, feats, W_eh, b_eh);     // 1
    k_wsplit<<<(W_TOT + 255) / 256, 256>>>(W_cat, Ws1, Wf1, Ws2, Wf2); // 2
    // concat projection (HMMA) at profiled slot #3
    k_mma<MAPD + H, true, true, false><<<MB, 256, MMA_SMEM>>>(     // 3
        maps, hemb, wh, wl, b_cat, hA, nullptr);
    k_scan<<<1, 1024>>>();                                         // 4
    k_scatter<<<EB, 256>>>(src, dst);                              // 5

    // GAT layer 1: hA -> hB
    k_mma<H, false, false, true><<<dim3(MB, 2), 256, MMA_SMEM>>>(  // 6
        hA, nullptr, wh + 81920, wl + 81920, nullptr, hs, z);
    k_sdot<<<WB, 256>>>(a1);                                       // 7
    k_gat<false><<<WB, 256>>>(hA, hB, nullptr, nullptr, nullptr);  // 8

    // GAT layer 2 + fused output projection: hB -> out
    k_mma<H, false, false, true><<<dim3(MB, 2), 256, MMA_SMEM>>>(  // 9
        hB, nullptr, wh + 81920 + 32768, wl + 81920 + 32768, nullptr, hs, z);
    k_sdot<<<WB, 256>>>(a2);                                       // 10
    k_gat<true><<<WB, 256>>>(hB, nullptr, W_out, b_out, out);      // 11
}

// round 15
// speedup vs baseline: 1.0009x; 1.0009x over previous
#include <cuda_runtime.h>
#include <cuda_bf16.h>
#include <cstdint>

#define N_NODES 20000
#define E_EDGES 640000
#define IN_DIM  24
#define H       128
#define OUT_DIM 24
#define MAPD    512

typedef unsigned long long u64;

// ---------------- mma / ldmatrix helpers (baseline PTX, compute_103-safe) ----------------
__device__ __forceinline__ unsigned smem_u32(const void* p) {
    unsigned r;
    asm("{.reg .u64 t; cvta.to.shared.u64 t, %1; cvt.u32.u64 %0, t;}" : "=r"(r) : "l"(p));
    return r;
}
__device__ __forceinline__ void ldsm_x4(unsigned* r, unsigned addr) {
    asm volatile("ldmatrix.sync.aligned.m8n8.x4.shared.b16 {%0,%1,%2,%3}, [%4];"
                 : "=r"(r[0]), "=r"(r[1]), "=r"(r[2]), "=r"(r[3]) : "r"(addr));
}
__device__ __forceinline__ void mma16816(float* c, const unsigned* a, unsigned b0, unsigned b1) {
    asm volatile(
        "mma.sync.aligned.m16n8k16.row.col.f32.bf16.bf16.f32 "
        "{%0,%1,%2,%3}, {%4,%5,%6,%7}, {%8,%9}, {%0,%1,%2,%3};"
        : "+f"(c[0]), "+f"(c[1]), "+f"(c[2]), "+f"(c[3])
        : "r"(a[0]), "r"(a[1]), "r"(a[2]), "r"(a[3]), "r"(b0), "r"(b1));
}
__device__ __forceinline__ unsigned pack_bf2(float x, float y) {
    __nv_bfloat162 t = __floats2bfloat162_rn(x, y);
    return *(unsigned*)&t;
}

// ---------------- scratch ----------------
__device__ float g_hemb[N_NODES * H];
__device__ float g_hA[N_NODES * H];
__device__ float g_hB[N_NODES * H];
__device__ float g_hs[N_NODES * H];
__device__ float g_z[N_NODES * H];
__device__ float g_ssrc[N_NODES];
__device__ float g_sdst[N_NODES];
__device__ int   g_offs[N_NODES + 1];
__device__ int   g_cnt[N_NODES];
__device__ int   g_cur[N_NODES];
__device__ int   g_csrc[E_EDGES];
// pre-split weights: [Wcat 81920][Ws1 16384][Wf1 16384][Ws2 16384][Wf2 16384]
#define W_TOT (81920 + 4 * 16384)
__device__ __nv_bfloat16 g_Wh[W_TOT];
__device__ __nv_bfloat16 g_Wl[W_TOT];

// ---------------- CSR build ----------------
__global__ void k_zero() {
    int i = blockIdx.x * blockDim.x + threadIdx.x;
    if (i < N_NODES) { g_cnt[i] = 0; g_cur[i] = 0; }
}

__global__ void k_hist_embed(const int* __restrict__ dst,
                             const float* __restrict__ feats,
                             const float* __restrict__ W_eh,
                             const float* __restrict__ b_eh) {
    if (blockIdx.x < 2500) {
        int e = blockIdx.x * 256 + threadIdx.x;
        if (e < E_EDGES) atomicAdd(&g_cnt[dst[e]], 1);
        return;
    }
    int nb = blockIdx.x - 2500;
    __shared__ float f[2][IN_DIM];
    int half = threadIdx.x >> 7;
    int h = threadIdx.x & 127;
    int n = nb * 2 + half;
    if (h < IN_DIM) f[half][h] = feats[n * IN_DIM + h];
    __syncthreads();
    float acc = b_eh[h];
    #pragma unroll
    for (int k = 0; k < IN_DIM; k++) acc += f[half][k] * W_eh[h * IN_DIM + k];
    g_hemb[n * H + h] = acc;
}

__global__ void k_scan() {
    const int PER = 20;
    int t = threadIdx.x;
    int base = t * PER;
    int vals[PER];
    int s = 0;
    #pragma unroll
    for (int p = 0; p < PER; p++) {
        int i = base + p;
        int v = (i < N_NODES) ? g_cnt[i] : 0;
        vals[p] = s;
        s += v;
    }
    __shared__ int sh[1024];
    sh[t] = s;
    __syncthreads();
    #pragma unroll
    for (int off = 1; off < 1024; off <<= 1) {
        int x = (t >= off) ? sh[t - off] : 0;
        __syncthreads();
        sh[t] += x;
        __syncthreads();
    }
    int excl = sh[t] - s;
    #pragma unroll
    for (int p = 0; p < PER; p++) {
        int i = base + p;
        if (i < N_NODES) g_offs[i] = excl + vals[p];
    }
    if (t == 1023) g_offs[N_NODES] = sh[1023];
}

__global__ void k_scatter(const int* __restrict__ src, const int* __restrict__ dst) {
    int e = blockIdx.x * blockDim.x + threadIdx.x;
    if (e < E_EDGES) {
        int d = dst[e];
        int p = g_offs[d] + atomicAdd(&g_cur[d], 1);
        g_csrc[p] = src[e];
    }
}

// ---------------- weight split prep ----------------
__global__ void k_wsplit(const float* __restrict__ Wcat, const float* __restrict__ Ws1,
                         const float* __restrict__ Wf1, const float* __restrict__ Ws2,
                         const float* __restrict__ Wf2) {
    int i = blockIdx.x * 256 + threadIdx.x;
    if (i >= W_TOT) return;
    float v;
    if (i < 81920) v = Wcat[i];
    else {
        int j = i - 81920;
        int m = j >> 14, o = j & 16383;
        v = (m == 0 ? Ws1 : (m == 1 ? Wf1 : (m == 2 ? Ws2 : Wf2)))[o];
    }
    __nv_bfloat16 h = __float2bfloat16(v);
    __nv_bfloat16 l = __float2bfloat16(v - __bfloat162float(h));
    g_Wh[i] = h;
    g_Wl[i] = l;
}

// ---------------- HMMA bf16x3-split GEMM ----------------
// C[row0:row0+128, 0:128] = X @ W[128,KDIM]^T (+bias+relu)
// 8 warps: wm = wid&3 (32 rows), wn = wid>>2 (64 cols)
// smem: AH/AL [128][64] bf16 (16KB each), BH/BL [128][64] bf16 (16KB each) = 64KB
template <int KDIM, bool CONCAT, bool BIASRELU, bool DUAL>
__global__ void __launch_bounds__(256)
k_mma(const float* __restrict__ A0, const float* __restrict__ A1,
      const __nv_bfloat16* __restrict__ WhB, const __nv_bfloat16* __restrict__ WlB,
      const float* __restrict__ bias,
      float* __restrict__ C0, float* __restrict__ C1) {
    extern __shared__ char sm[];
    const unsigned OFF_AH = 0, OFF_AL = 16384, OFF_BH = 32768, OFF_BL = 49152;
    unsigned sb = smem_u32(sm);

    int tid = threadIdx.x, lane = tid & 31, wid = tid >> 5;
    int wm = wid & 3, wn = wid >> 2;
    int y = DUAL ? blockIdx.y : 0;
    const __nv_bfloat16* Wh = WhB + (DUAL ? y * (128 * KDIM) : 0);
    const __nv_bfloat16* Wl = WlB + (DUAL ? y * (128 * KDIM) : 0);
    float* C = DUAL ? (y ? C1 : C0) : C0;
    int row0 = blockIdx.x * 128;

    float acc[2][8][4];
    #pragma unroll
    for (int i = 0; i < 2; i++)
        #pragma unroll
        for (int j = 0; j < 8; j++)
            #pragma unroll
            for (int q = 0; q < 4; q++) acc[i][j][q] = 0.f;

    // ldmatrix address precompute
    // A: matrix layout: khalf = lane>>4, rowhalf = (lane>>3)&1, r8 = lane&7
    int a_rh = (lane >> 3) & 1, a_kh = lane >> 4, r8 = lane & 7;
    int rowA[2], xorA[2];
    #pragma unroll
    for (int mt = 0; mt < 2; mt++) {
        rowA[mt] = wm * 32 + mt * 16 + a_rh * 8 + r8;
        xorA[mt] = rowA[mt] & 7;
    }
    // B: nhalf = (lane>>4)&1, khalf = (lane>>3)&1
    int b_nh = (lane >> 4) & 1, b_kh = (lane >> 3) & 1;
    int rowB[4], xorB[4];
    #pragma unroll
    for (int nt2 = 0; nt2 < 4; nt2++) {
        rowB[nt2] = wn * 64 + nt2 * 16 + b_nh * 8 + r8;
        xorB[nt2] = rowB[nt2] & 7;
    }

    const int NT = KDIM / 64;
    for (int kt = 0; kt < NT; kt++) {
        int k0 = kt * 64;
        // --- A tile: 128x64 fp32 -> hi/lo bf16, swizzled ---
        #pragma unroll
        for (int p = 0; p < 8; p++) {
            int idx = tid + p * 256;
            int row = idx >> 4, c4 = idx & 15;
            int grow = row0 + row, gk = k0 + c4 * 4;
            float4 v = make_float4(0.f, 0.f, 0.f, 0.f);
            if (grow < N_NODES) {
                if (CONCAT) v = (gk < MAPD) ? *(const float4*)&A0[grow * MAPD + gk]
                                            : *(const float4*)&A1[grow * H + (gk - MAPD)];
                else        v = *(const float4*)&A0[grow * KDIM + gk];
            }
            unsigned h0 = pack_bf2(v.x, v.y), h1 = pack_bf2(v.z, v.w);
            float rx = v.x - __bfloat162float(__float2bfloat16(v.x));
            float ry = v.y - __bfloat162float(__float2bfloat16(v.y));
            float rz = v.z - __bfloat162float(__float2bfloat16(v.z));
            float rw = v.w - __bfloat162float(__float2bfloat16(v.w));
            unsigned l0 = pack_bf2(rx, ry), l1 = pack_bf2(rz, rw);
            unsigned off = row * 128 + c4 * 8;
            unsigned sw = off ^ ((row & 7) << 4);
            *(uint2*)(sm + OFF_AH + sw) = make_uint2(h0, h1);
            *(uint2*)(sm + OFF_AL + sw) = make_uint2(l0, l1);
        }
        // --- B tile: 128x64 bf16 hi/lo (pre-split), swizzled ---
        #pragma unroll
        for (int p = 0; p < 4; p++) {
            int idx = tid + p * 256;
            int row = idx >> 3, c16 = idx & 7;
            unsigned off = row * 128 + c16 * 16;
            unsigned sw = off ^ ((row & 7) << 4);
            const __nv_bfloat16* gh = &Wh[row * KDIM + k0 + c16 * 8];
            const __nv_bfloat16* gl = &Wl[row * KDIM + k0 + c16 * 8];
            *(uint4*)(sm + OFF_BH + sw) = *(const uint4*)gh;
            *(uint4*)(sm + OFF_BL + sw) = *(const uint4*)gl;
        }
        __syncthreads();

        #pragma unroll
        for (int ks = 0; ks < 4; ks++) {
            unsigned ah[2][4], al[2][4];
            #pragma unroll
            for (int mt = 0; mt < 2; mt++) {
                unsigned chunk = (ks * 2 + a_kh) ^ xorA[mt];
                unsigned o = rowA[mt] * 128 + chunk * 16;
                ldsm_x4(ah[mt], sb + OFF_AH + o);
                ldsm_x4(al[mt], sb + OFF_AL + o);
            }
            unsigned bh[4][4], bl[4][4];
            #pragma unroll
            for (int nt2 = 0; nt2 < 4; nt2++) {
                unsigned chunk = (ks * 2 + b_kh) ^ xorB[nt2];
                unsigned o = rowB[nt2] * 128 + chunk * 16;
                ldsm_x4(bh[nt2], sb + OFF_BH + o);
                ldsm_x4(bl[nt2], sb + OFF_BL + o);
            }
            #pragma unroll
            for (int mt = 0; mt < 2; mt++)
                #pragma unroll
                for (int nt = 0; nt < 8; nt++) {
                    float* c = acc[mt][nt];
                    unsigned s = (nt & 1) * 2;
                    const unsigned* BH_ = bh[nt >> 1];
                    const unsigned* BL_ = bl[nt >> 1];
                    mma16816(c, ah[mt], BH_[s], BH_[s + 1]);
                    mma16816(c, ah[mt], BL_[s], BL_[s + 1]);
                    mma16816(c, al[mt], BH_[s], BH_[s + 1]);
                }
        }
        __syncthreads();
    }

    // --- epilogue ---
    int cbase = wn * 64 + (lane & 3) * 2;
    int rbase = row0 + wm * 32 + (lane >> 2);
    #pragma unroll
    for (int mt = 0; mt < 2; mt++) {
        #pragma unroll
        for (int nt = 0; nt < 8; nt++) {
            int col = cbase + nt * 8;
            float b0 = 0.f, b1 = 0.f;
            if (BIASRELU) { b0 = bias[col]; b1 = bias[col + 1]; }
            int r0 = rbase + mt * 16;
            int r1 = r0 + 8;
            float* c = acc[mt][nt];
            if (r0 < N_NODES) {
                float2 v = make_float2(c[0] + b0, c[1] + b1);
                if (BIASRELU) { v.x = fmaxf(v.x, 0.f); v.y = fmaxf(v.y, 0.f); }
                *(float2*)&C[r0 * H + col] = v;
            }
            if (r1 < N_NODES) {
                float2 v = make_float2(c[2] + b0, c[3] + b1);
                if (BIASRELU) { v.x = fmaxf(v.x, 0.f); v.y = fmaxf(v.y, 0.f); }
                *(float2*)&C[r1 * H + col] = v;
            }
        }
    }
}
#define MMA_SMEM 65536

// ---------------- per-node attention halves ----------------
__global__ void k_sdot(const float* __restrict__ a) {
    int warp = (blockIdx.x * blockDim.x + threadIdx.x) >> 5;
    int lane = threadIdx.x & 31;
    if (warp >= N_NODES) return;
    float4 zv = *(const float4*)&g_z[warp * H + lane * 4];
    float4 a0 = *(const float4*)&a[lane * 4];
    float4 a1 = *(const float4*)&a[H + lane * 4];
    float s0 = zv.x * a0.x + zv.y * a0.y + zv.z * a0.z + zv.w * a0.w;
    float s1 = zv.x * a1.x + zv.y * a1.y + zv.z * a1.z + zv.w * a1.w;
    #pragma unroll
    for (int off = 16; off; off >>= 1) {
        s0 += __shfl_xor_sync(0xffffffffu, s0, off);
        s1 += __shfl_xor_sync(0xffffffffu, s1, off);
    }
    if (lane == 0) { g_ssrc[warp] = s0; g_sdst[warp] = s1; }
}

// ---------------- fused GAT edge kernel (warp/node); optional out-proj epilogue ----------------
template <bool DO_OUT>
__global__ void k_gat(const float* __restrict__ hin, float* __restrict__ hout,
                      const float* __restrict__ Wout, const float* __restrict__ bout,
                      float* __restrict__ out) {
    __shared__ float ws[DO_OUT ? OUT_DIM * H : 1];
    __shared__ float bs[DO_OUT ? OUT_DIM : 1];
    if (DO_OUT) {
        for (int i = threadIdx.x; i < OUT_DIM * H; i += blockDim.x) ws[i] = Wout[i];
        if (threadIdx.x < OUT_DIM) bs[threadIdx.x] = bout[threadIdx.x];
        __syncthreads();
    }
    int node = blockIdx.x * (blockDim.x >> 5) + (threadIdx.x >> 5);
    int lane = threadIdx.x & 31;
    if (node >= N_NODES) return;
    int beg = g_offs[node], end = g_offs[node + 1];
    float4 hi = *(const float4*)&hin[node * H + lane * 4];
    float4 o4;
    if (beg == end) {
        o4 = make_float4(2.f * hi.x, 2.f * hi.y, 2.f * hi.z, 2.f * hi.w);
    } else {
        float sd = g_sdst[node];
        float mx = -3.0e38f;
        for (int j = beg + lane; j < end; j += 32) {
            float x = g_ssrc[g_csrc[j]] + sd;
            mx = fmaxf(mx, fmaxf(x, 0.01f * x));
        }
        #pragma unroll
        for (int off = 16; off; off >>= 1) mx = fmaxf(mx, __shfl_xor_sync(0xffffffffu, mx, off));
        float den = 0.f;
        for (int j = beg + lane; j < end; j += 32) {
            float x = g_ssrc[g_csrc[j]] + sd;
            den += __expf(fmaxf(x, 0.01f * x) - mx);
        }
        #pragma unroll
        for (int off = 16; off; off >>= 1) den += __shfl_xor_sync(0xffffffffu, den, off);
        float invden = 1.f / fmaxf(den, 1e-16f);
        float4 acc = make_float4(0.f, 0.f, 0.f, 0.f);
        for (int base = beg; base < end; base += 32) {
            int j = base + lane;
            float coeff = 0.f; int s = 0;
            if (j < end) {
                s = g_csrc[j];
                float x = g_ssrc[s] + sd;
                coeff = __expf(fmaxf(x, 0.01f * x) - mx) * invden;
            }
            int cnt = min(32, end - base);
            if (cnt == 32) {
                #pragma unroll 8
                for (int t = 0; t < 32; t++) {
                    float c = __shfl_sync(0xffffffffu, coeff, t);
                    int ss = __shfl_sync(0xffffffffu, s, t);
                    float4 zv = *(const float4*)&g_z[ss * H + lane * 4];
                    acc.x += c * zv.x; acc.y += c * zv.y;
                    acc.z += c * zv.z; acc.w += c * zv.w;
                }
            } else {
                for (int t = 0; t < cnt; t++) {
                    float c = __shfl_sync(0xffffffffu, coeff, t);
                    int ss = __shfl_sync(0xffffffffu, s, t);
                    float4 zv = *(const float4*)&g_z[ss * H + lane * 4];
                    acc.x += c * zv.x; acc.y += c * zv.y;
                    acc.z += c * zv.z; acc.w += c * zv.w;
                }
            }
        }
        float4 hs = *(const float4*)&g_hs[node * H + lane * 4];
        o4 = make_float4(hi.x + hs.x + acc.x, hi.y + hs.y + acc.y,
                         hi.z + hs.z + acc.z, hi.w + hs.w + acc.w);
    }
    if (!DO_OUT) {
        *(float4*)&hout[node * H + lane * 4] = o4;
    } else {
        float vout = 0.f;
        #pragma unroll
        for (int o = 0; o < OUT_DIM; o++) {
            float4 wv = *(const float4*)&ws[o * H + lane * 4];
            float p = o4.x * wv.x + o4.y * wv.y + o4.z * wv.z + o4.w * wv.w;
            #pragma unroll
            for (int off = 16; off; off >>= 1) p += __shfl_xor_sync(0xffffffffu, p, off);
            if (lane == o) vout = p + bs[o];
        }
        if (lane < OUT_DIM) out[node * OUT_DIM + lane] = vout;
    }
}

// ---------------- launch ----------------
extern "C" void kernel_launch(void* const* d_in, const int* in_sizes, int n_in,
                              void* d_out, int out_size) {
    const float* feats = (const float*)d_in[0];
    const float* maps  = (const float*)d_in[2];
    const int*   src   = (const int*)d_in[4];
    const int*   dst   = (const int*)d_in[5];
    const float* W_eh  = (const float*)d_in[6];
    const float* b_eh  = (const float*)d_in[7];
    const float* W_cat = (const float*)d_in[10];
    const float* b_cat = (const float*)d_in[11];
    const float* Ws1   = (const float*)d_in[12];
    const float* Wf1   = (const float*)d_in[13];
    const float* a1    = (const float*)d_in[14];
    const float* Ws2   = (const float*)d_in[15];
    const float* Wf2   = (const float*)d_in[16];
    const float* a2    = (const float*)d_in[17];
    const float* W_out = (const float*)d_in[18];
    const float* b_out = (const float*)d_in[19];
    float* out = (float*)d_out;

    float *hemb, *hA, *hB, *hs, *z;
    cudaGetSymbolAddress((void**)&hemb, g_hemb);
    cudaGetSymbolAddress((void**)&hA, g_hA);
    cudaGetSymbolAddress((void**)&hB, g_hB);
    cudaGetSymbolAddress((void**)&hs, g_hs);
    cudaGetSymbolAddress((void**)&z,  g_z);
    __nv_bfloat16 *wh, *wl;
    cudaGetSymbolAddress((void**)&wh, g_Wh);
    cudaGetSymbolAddress((void**)&wl, g_Wl);

    cudaFuncSetAttribute(k_mma<MAPD + H, true, true, false>,
                         cudaFuncAttributeMaxDynamicSharedMemorySize, MMA_SMEM);
    cudaFuncSetAttribute(k_mma<H, false, false, true>,
                         cudaFuncAttributeMaxDynamicSharedMemorySize, MMA_SMEM);

    const int MB = (N_NODES + 127) / 128; // 157
    const int EB = (E_EDGES + 255) / 256; // 2500
    const int WB = (N_NODES + 7) / 8;     // 2500

    k_zero<<<(N_NODES + 255) / 256, 256>>>();                      // 0
    k_hist_embed<<<EB + 10000, 256>>>(dst, feats, W_eh, b_eh);     // 1
    k_wsplit<<<(W_TOT + 255) / 256, 256>>>(W_cat, Ws1, Wf1, Ws2, Wf2); // 2
    // concat projection (HMMA) at profiled slot #3
    k_mma<MAPD + H, true, true, false><<<MB, 256, MMA_SMEM>>>(     // 3
        maps, hemb, wh, wl, b_cat, hA, nullptr);
    k_scan<<<1, 1024>>>();                                         // 4
    k_scatter<<<EB, 256>>>(src, dst);                              // 5

    // GAT layer 1: hA -> hB
    k_mma<H, false, false, true><<<dim3(MB, 2), 256, MMA_SMEM>>>(  // 6
        hA, nullptr, wh + 81920, wl + 81920, nullptr, hs, z);
    k_sdot<<<WB, 256>>>(a1);                                       // 7
    k_gat<false><<<WB, 256>>>(hA, hB, nullptr, nullptr, nullptr);  // 8

    // GAT layer 2 + fused output projection: hB -> out
    k_mma<H, false, false, true><<<dim3(MB, 2), 256, MMA_SMEM>>>(  // 9
        hB, nullptr, wh + 81920 + 32768, wl + 81920 + 32768, nullptr, hs, z);
    k_sdot<<<WB, 256>>>(a2);                                       // 10
    k_gat<true><<<WB, 256>>>(hB, nullptr, W_out, b_out, out);      // 11
}

// round 16
// speedup vs baseline: 1.0082x; 1.0072x over previous
#include <cuda_runtime.h>
#include <cuda_bf16.h>
#include <cstdint>

#define N_NODES 20000
#define E_EDGES 640000
#define IN_DIM  24
#define H       128
#define OUT_DIM 24
#define MAPD    512

typedef unsigned long long u64;

// ---------------- mma / ldmatrix helpers (baseline PTX, compute_103-safe) ----------------
__device__ __forceinline__ unsigned smem_u32(const void* p) {
    unsigned r;
    asm("{.reg .u64 t; cvta.to.shared.u64 t, %1; cvt.u32.u64 %0, t;}" : "=r"(r) : "l"(p));
    return r;
}
__device__ __forceinline__ void ldsm_x4(unsigned* r, unsigned addr) {
    asm volatile("ldmatrix.sync.aligned.m8n8.x4.shared.b16 {%0,%1,%2,%3}, [%4];"
                 : "=r"(r[0]), "=r"(r[1]), "=r"(r[2]), "=r"(r[3]) : "r"(addr));
}
__device__ __forceinline__ void mma16816(float* c, const unsigned* a, unsigned b0, unsigned b1) {
    asm volatile(
        "mma.sync.aligned.m16n8k16.row.col.f32.bf16.bf16.f32 "
        "{%0,%1,%2,%3}, {%4,%5,%6,%7}, {%8,%9}, {%0,%1,%2,%3};"
        : "+f"(c[0]), "+f"(c[1]), "+f"(c[2]), "+f"(c[3])
        : "r"(a[0]), "r"(a[1]), "r"(a[2]), "r"(a[3]), "r"(b0), "r"(b1));
}
__device__ __forceinline__ unsigned pack_bf2(float x, float y) {
    __nv_bfloat162 t = __floats2bfloat162_rn(x, y);
    return *(unsigned*)&t;
}

// ---------------- scratch ----------------
__device__ float g_hemb[N_NODES * H];
__device__ float g_hA[N_NODES * H];
__device__ float g_hB[N_NODES * H];
__device__ float g_hs[N_NODES * H];
__device__ float g_z[N_NODES * H];
__device__ float g_ssrc[N_NODES];
__device__ float g_sdst[N_NODES];
__device__ int   g_offs[N_NODES + 1];
__device__ int   g_cnt[N_NODES];
__device__ int   g_cur[N_NODES];
__device__ int   g_csrc[E_EDGES];
// pre-split weights: [Wcat 81920][Ws1 16384][Wf1 16384][Ws2 16384][Wf2 16384]
#define W_TOT (81920 + 4 * 16384)
__device__ __nv_bfloat16 g_Wh[W_TOT];
__device__ __nv_bfloat16 g_Wl[W_TOT];

// ---------------- CSR build ----------------
__global__ void k_zero() {
    int i = blockIdx.x * blockDim.x + threadIdx.x;
    if (i < N_NODES) { g_cnt[i] = 0; g_cur[i] = 0; }
}

__global__ void k_hist_embed(const int* __restrict__ dst,
                             const float* __restrict__ feats,
                             const float* __restrict__ W_eh,
                             const float* __restrict__ b_eh) {
    if (blockIdx.x < 2500) {
        int e = blockIdx.x * 256 + threadIdx.x;
        if (e < E_EDGES) atomicAdd(&g_cnt[dst[e]], 1);
        return;
    }
    int nb = blockIdx.x - 2500;
    __shared__ float f[2][IN_DIM];
    int half = threadIdx.x >> 7;
    int h = threadIdx.x & 127;
    int n = nb * 2 + half;
    if (h < IN_DIM) f[half][h] = feats[n * IN_DIM + h];
    __syncthreads();
    float acc = b_eh[h];
    #pragma unroll
    for (int k = 0; k < IN_DIM; k++) acc += f[half][k] * W_eh[h * IN_DIM + k];
    g_hemb[n * H + h] = acc;
}

__global__ void k_scan() {
    const int PER = 20;
    int t = threadIdx.x;
    int base = t * PER;
    int vals[PER];
    int s = 0;
    #pragma unroll
    for (int p = 0; p < PER; p++) {
        int i = base + p;
        int v = (i < N_NODES) ? g_cnt[i] : 0;
        vals[p] = s;
        s += v;
    }
    __shared__ int sh[1024];
    sh[t] = s;
    __syncthreads();
    #pragma unroll
    for (int off = 1; off < 1024; off <<= 1) {
        int x = (t >= off) ? sh[t - off] : 0;
        __syncthreads();
        sh[t] += x;
        __syncthreads();
    }
    int excl = sh[t] - s;
    #pragma unroll
    for (int p = 0; p < PER; p++) {
        int i = base + p;
        if (i < N_NODES) g_offs[i] = excl + vals[p];
    }
    if (t == 1023) g_offs[N_NODES] = sh[1023];
}

__global__ void k_scatter(const int* __restrict__ src, const int* __restrict__ dst) {
    int e = blockIdx.x * blockDim.x + threadIdx.x;
    if (e < E_EDGES) {
        int d = dst[e];
        int p = g_offs[d] + atomicAdd(&g_cur[d], 1);
        g_csrc[p] = src[e];
    }
}

// ---------------- weight split prep ----------------
__global__ void k_wsplit(const float* __restrict__ Wcat, const float* __restrict__ Ws1,
                         const float* __restrict__ Wf1, const float* __restrict__ Ws2,
                         const float* __restrict__ Wf2) {
    int i = blockIdx.x * 256 + threadIdx.x;
    if (i >= W_TOT) return;
    float v;
    if (i < 81920) v = Wcat[i];
    else {
        int j = i - 81920;
        int m = j >> 14, o = j & 16383;
        v = (m == 0 ? Ws1 : (m == 1 ? Wf1 : (m == 2 ? Ws2 : Wf2)))[o];
    }
    __nv_bfloat16 h = __float2bfloat16(v);
    __nv_bfloat16 l = __float2bfloat16(v - __bfloat162float(h));
    g_Wh[i] = h;
    g_Wl[i] = l;
}

// ---------------- HMMA bf16x3-split GEMM ----------------
// C[row0:row0+128, 0:128] = X @ W[128,KDIM]^T (+bias+relu)
// 8 warps: wm = wid&3 (32 rows), wn = wid>>2 (64 cols)
// smem: AH/AL [128][64] bf16 (16KB each), BH/BL [128][64] bf16 (16KB each) = 64KB
template <int KDIM, bool CONCAT, bool BIASRELU, bool DUAL>
__global__ void __launch_bounds__(256)
k_mma(const float* __restrict__ A0, const float* __restrict__ A1,
      const __nv_bfloat16* __restrict__ WhB, const __nv_bfloat16* __restrict__ WlB,
      const float* __restrict__ bias,
      float* __restrict__ C0, float* __restrict__ C1) {
    extern __shared__ char sm[];
    const unsigned OFF_AH = 0, OFF_AL = 16384, OFF_BH = 32768, OFF_BL = 49152;
    unsigned sb = smem_u32(sm);

    int tid = threadIdx.x, lane = tid & 31, wid = tid >> 5;
    int wm = wid & 3, wn = wid >> 2;
    int y = DUAL ? blockIdx.y : 0;
    const __nv_bfloat16* Wh = WhB + (DUAL ? y * (128 * KDIM) : 0);
    const __nv_bfloat16* Wl = WlB + (DUAL ? y * (128 * KDIM) : 0);
    float* C = DUAL ? (y ? C1 : C0) : C0;
    int row0 = blockIdx.x * 128;

    float acc[2][8][4];
    #pragma unroll
    for (int i = 0; i < 2; i++)
        #pragma unroll
        for (int j = 0; j < 8; j++)
            #pragma unroll
            for (int q = 0; q < 4; q++) acc[i][j][q] = 0.f;

    // ldmatrix address precompute
    // A: matrix layout: khalf = lane>>4, rowhalf = (lane>>3)&1, r8 = lane&7
    int a_rh = (lane >> 3) & 1, a_kh = lane >> 4, r8 = lane & 7;
    int rowA[2], xorA[2];
    #pragma unroll
    for (int mt = 0; mt < 2; mt++) {
        rowA[mt] = wm * 32 + mt * 16 + a_rh * 8 + r8;
        xorA[mt] = rowA[mt] & 7;
    }
    // B: nhalf = (lane>>4)&1, khalf = (lane>>3)&1
    int b_nh = (lane >> 4) & 1, b_kh = (lane >> 3) & 1;
    int rowB[4], xorB[4];
    #pragma unroll
    for (int nt2 = 0; nt2 < 4; nt2++) {
        rowB[nt2] = wn * 64 + nt2 * 16 + b_nh * 8 + r8;
        xorB[nt2] = rowB[nt2] & 7;
    }

    const int NT = KDIM / 64;
    for (int kt = 0; kt < NT; kt++) {
        int k0 = kt * 64;
        // --- A tile: 128x64 fp32 -> hi/lo bf16, swizzled ---
        #pragma unroll
        for (int p = 0; p < 8; p++) {
            int idx = tid + p * 256;
            int row = idx >> 4, c4 = idx & 15;
            int grow = row0 + row, gk = k0 + c4 * 4;
            float4 v = make_float4(0.f, 0.f, 0.f, 0.f);
            if (grow < N_NODES) {
                if (CONCAT) v = (gk < MAPD) ? *(const float4*)&A0[grow * MAPD + gk]
                                            : *(const float4*)&A1[grow * H + (gk - MAPD)];
                else        v = *(const float4*)&A0[grow * KDIM + gk];
            }
            unsigned h0 = pack_bf2(v.x, v.y), h1 = pack_bf2(v.z, v.w);
            float rx = v.x - __bfloat162float(__float2bfloat16(v.x));
            float ry = v.y - __bfloat162float(__float2bfloat16(v.y));
            float rz = v.z - __bfloat162float(__float2bfloat16(v.z));
            float rw = v.w - __bfloat162float(__float2bfloat16(v.w));
            unsigned l0 = pack_bf2(rx, ry), l1 = pack_bf2(rz, rw);
            unsigned off = row * 128 + c4 * 8;
            unsigned sw = off ^ ((row & 7) << 4);
            *(uint2*)(sm + OFF_AH + sw) = make_uint2(h0, h1);
            *(uint2*)(sm + OFF_AL + sw) = make_uint2(l0, l1);
        }
        // --- B tile: 128x64 bf16 hi/lo (pre-split), swizzled ---
        #pragma unroll
        for (int p = 0; p < 4; p++) {
            int idx = tid + p * 256;
            int row = idx >> 3, c16 = idx & 7;
            unsigned off = row * 128 + c16 * 16;
            unsigned sw = off ^ ((row & 7) << 4);
            const __nv_bfloat16* gh = &Wh[row * KDIM + k0 + c16 * 8];
            const __nv_bfloat16* gl = &Wl[row * KDIM + k0 + c16 * 8];
            *(uint4*)(sm + OFF_BH + sw) = *(const uint4*)gh;
            *(uint4*)(sm + OFF_BL + sw) = *(const uint4*)gl;
        }
        __syncthreads();

        #pragma unroll
        for (int ks = 0; ks < 4; ks++) {
            unsigned ah[2][4], al[2][4];
            #pragma unroll
            for (int mt = 0; mt < 2; mt++) {
                unsigned chunk = (ks * 2 + a_kh) ^ xorA[mt];
                unsigned o = rowA[mt] * 128 + chunk * 16;
                ldsm_x4(ah[mt], sb + OFF_AH + o);
                ldsm_x4(al[mt], sb + OFF_AL + o);
            }
            unsigned bh[4][4], bl[4][4];
            #pragma unroll
            for (int nt2 = 0; nt2 < 4; nt2++) {
                unsigned chunk = (ks * 2 + b_kh) ^ xorB[nt2];
                unsigned o = rowB[nt2] * 128 + chunk * 16;
                ldsm_x4(bh[nt2], sb + OFF_BH + o);
                ldsm_x4(bl[nt2], sb + OFF_BL + o);
            }
            #pragma unroll
            for (int mt = 0; mt < 2; mt++)
                #pragma unroll
                for (int nt = 0; nt < 8; nt++) {
                    float* c = acc[mt][nt];
                    unsigned s = (nt & 1) * 2;
                    const unsigned* BH_ = bh[nt >> 1];
                    const unsigned* BL_ = bl[nt >> 1];
                    mma16816(c, ah[mt], BH_[s], BH_[s + 1]);
                    mma16816(c, ah[mt], BL_[s], BL_[s + 1]);
                    mma16816(c, al[mt], BH_[s], BH_[s + 1]);
                }
        }
        __syncthreads();
    }

    // --- epilogue ---
    int cbase = wn * 64 + (lane & 3) * 2;
    int rbase = row0 + wm * 32 + (lane >> 2);
    #pragma unroll
    for (int mt = 0; mt < 2; mt++) {
        #pragma unroll
        for (int nt = 0; nt < 8; nt++) {
            int col = cbase + nt * 8;
            float b0 = 0.f, b1 = 0.f;
            if (BIASRELU) { b0 = bias[col]; b1 = bias[col + 1]; }
            int r0 = rbase + mt * 16;
            int r1 = r0 + 8;
            float* c = acc[mt][nt];
            if (r0 < N_NODES) {
                float2 v = make_float2(c[0] + b0, c[1] + b1);
                if (BIASRELU) { v.x = fmaxf(v.x, 0.f); v.y = fmaxf(v.y, 0.f); }
                *(float2*)&C[r0 * H + col] = v;
            }
            if (r1 < N_NODES) {
                float2 v = make_float2(c[2] + b0, c[3] + b1);
                if (BIASRELU) { v.x = fmaxf(v.x, 0.f); v.y = fmaxf(v.y, 0.f); }
                *(float2*)&C[r1 * H + col] = v;
            }
        }
    }
}
#define MMA_SMEM 65536

// ---------------- per-node attention halves ----------------
__global__ void k_sdot(const float* __restrict__ a) {
    int warp = (blockIdx.x * blockDim.x + threadIdx.x) >> 5;
    int lane = threadIdx.x & 31;
    if (warp >= N_NODES) return;
    float4 zv = *(const float4*)&g_z[warp * H + lane * 4];
    float4 a0 = *(const float4*)&a[lane * 4];
    float4 a1 = *(const float4*)&a[H + lane * 4];
    float s0 = zv.x * a0.x + zv.y * a0.y + zv.z * a0.z + zv.w * a0.w;
    float s1 = zv.x * a1.x + zv.y * a1.y + zv.z * a1.z + zv.w * a1.w;
    #pragma unroll
    for (int off = 16; off; off >>= 1) {
        s0 += __shfl_xor_sync(0xffffffffu, s0, off);
        s1 += __shfl_xor_sync(0xffffffffu, s1, off);
    }
    if (lane == 0) { g_ssrc[warp] = s0; g_sdst[warp] = s1; }
}

// ---------------- fused GAT edge kernel (warp/node); optional out-proj epilogue ----------------
template <bool DO_OUT>
__global__ void k_gat(const float* __restrict__ hin, float* __restrict__ hout,
                      const float* __restrict__ Wout, const float* __restrict__ bout,
                      float* __restrict__ out) {
    __shared__ float ws[DO_OUT ? OUT_DIM * H : 1];
    __shared__ float bs[DO_OUT ? OUT_DIM : 1];
    if (DO_OUT) {
        for (int i = threadIdx.x; i < OUT_DIM * H; i += blockDim.x) ws[i] = Wout[i];
        if (threadIdx.x < OUT_DIM) bs[threadIdx.x] = bout[threadIdx.x];
        __syncthreads();
    }
    int node = blockIdx.x * (blockDim.x >> 5) + (threadIdx.x >> 5);
    int lane = threadIdx.x & 31;
    if (node >= N_NODES) return;
    int beg = g_offs[node], end = g_offs[node + 1];
    float4 hi = *(const float4*)&hin[node * H + lane * 4];
    float4 o4;
    if (beg == end) {
        o4 = make_float4(2.f * hi.x, 2.f * hi.y, 2.f * hi.z, 2.f * hi.w);
    } else {
        float sd = g_sdst[node];
        float mx = -3.0e38f;
        for (int j = beg + lane; j < end; j += 32) {
            float x = g_ssrc[g_csrc[j]] + sd;
            mx = fmaxf(mx, fmaxf(x, 0.01f * x));
        }
        #pragma unroll
        for (int off = 16; off; off >>= 1) mx = fmaxf(mx, __shfl_xor_sync(0xffffffffu, mx, off));
        float den = 0.f;
        for (int j = beg + lane; j < end; j += 32) {
            float x = g_ssrc[g_csrc[j]] + sd;
            den += __expf(fmaxf(x, 0.01f * x) - mx);
        }
        #pragma unroll
        for (int off = 16; off; off >>= 1) den += __shfl_xor_sync(0xffffffffu, den, off);
        float invden = 1.f / fmaxf(den, 1e-16f);
        float4 acc = make_float4(0.f, 0.f, 0.f, 0.f);
        for (int base = beg; base < end; base += 32) {
            int j = base + lane;
            float coeff = 0.f; int s = 0;
            if (j < end) {
                s = g_csrc[j];
                float x = g_ssrc[s] + sd;
                coeff = __expf(fmaxf(x, 0.01f * x) - mx) * invden;
            }
            int cnt = min(32, end - base);
            if (cnt == 32) {
                #pragma unroll 8
                for (int t = 0; t < 32; t++) {
                    float c = __shfl_sync(0xffffffffu, coeff, t);
                    int ss = __shfl_sync(0xffffffffu, s, t);
                    float4 zv = *(const float4*)&g_z[ss * H + lane * 4];
                    acc.x += c * zv.x; acc.y += c * zv.y;
                    acc.z += c * zv.z; acc.w += c * zv.w;
                }
            } else {
                for (int t = 0; t < cnt; t++) {
                    float c = __shfl_sync(0xffffffffu, coeff, t);
                    int ss = __shfl_sync(0xffffffffu, s, t);
                    float4 zv = *(const float4*)&g_z[ss * H + lane * 4];
                    acc.x += c * zv.x; acc.y += c * zv.y;
                    acc.z += c * zv.z; acc.w += c * zv.w;
                }
            }
        }
        float4 hs = *(const float4*)&g_hs[node * H + lane * 4];
        o4 = make_float4(hi.x + hs.x + acc.x, hi.y + hs.y + acc.y,
                         hi.z + hs.z + acc.z, hi.w + hs.w + acc.w);
    }
    if (!DO_OUT) {
        *(float4*)&hout[node * H + lane * 4] = o4;
    } else {
        float vout = 0.f;
        #pragma unroll
        for (int o = 0; o < OUT_DIM; o++) {
            float4 wv = *(const float4*)&ws[o * H + lane * 4];
            float p = o4.x * wv.x + o4.y * wv.y + o4.z * wv.z + o4.w * wv.w;
            #pragma unroll
            for (int off = 16; off; off >>= 1) p += __shfl_xor_sync(0xffffffffu, p, off);
            if (lane == o) vout = p + bs[o];
        }
        if (lane < OUT_DIM) out[node * OUT_DIM + lane] = vout;
    }
}

// ---------------- launch ----------------
extern "C" void kernel_launch(void* const* d_in, const int* in_sizes, int n_in,
                              void* d_out, int out_size) {
    const float* feats = (const float*)d_in[0];
    const float* maps  = (const float*)d_in[2];
    const int*   src   = (const int*)d_in[4];
    const int*   dst   = (const int*)d_in[5];
    const float* W_eh  = (const float*)d_in[6];
    const float* b_eh  = (const float*)d_in[7];
    const float* W_cat = (const float*)d_in[10];
    const float* b_cat = (const float*)d_in[11];
    const float* Ws1   = (const float*)d_in[12];
    const float* Wf1   = (const float*)d_in[13];
    const float* a1    = (const float*)d_in[14];
    const float* Ws2   = (const float*)d_in[15];
    const float* Wf2   = (const float*)d_in[16];
    const float* a2    = (const float*)d_in[17];
    const float* W_out = (const float*)d_in[18];
    const float* b_out = (const float*)d_in[19];
    float* out = (float*)d_out;

    float *hemb, *hA, *hB, *hs, *z;
    cudaGetSymbolAddress((void**)&hemb, g_hemb);
    cudaGetSymbolAddress((void**)&hA, g_hA);
    cudaGetSymbolAddress((void**)&hB, g_hB);
    cudaGetSymbolAddress((void**)&hs, g_hs);
    cudaGetSymbolAddress((void**)&z,  g_z);
    __nv_bfloat16 *wh, *wl;
    cudaGetSymbolAddress((void**)&wh, g_Wh);
    cudaGetSymbolAddress((void**)&wl, g_Wl);

    cudaFuncSetAttribute(k_mma<MAPD + H, true, true, false>,
                         cudaFuncAttributeMaxDynamicSharedMemorySize, MMA_SMEM);
    cudaFuncSetAttribute(k_mma<H, false, false, true>,
                         cudaFuncAttributeMaxDynamicSharedMemorySize, MMA_SMEM);

    const int MB = (N_NODES + 127) / 128; // 157
    const int EB = (E_EDGES + 255) / 256; // 2500
    const int WB = (N_NODES + 7) / 8;     // 2500

    k_zero<<<(N_NODES + 255) / 256, 256>>>();                      // 0
    k_hist_embed<<<EB + 10000, 256>>>(dst, feats, W_eh, b_eh);     // 1
    k_wsplit<<<(W_TOT + 255) / 256, 256>>>(W_cat, Ws1, Wf1, Ws2, Wf2); // 2
    // concat projection (HMMA) at profiled slot #3
    k_mma<MAPD + H, true, true, false><<<MB, 256, MMA_SMEM>>>(     // 3
        maps, hemb, wh, wl, b_cat, hA, nullptr);
    k_scan<<<1, 1024>>>();                                         // 4
    k_scatter<<<EB, 256>>>(src, dst);                              // 5

    // GAT layer 1: hA -> hB
    k_mma<H, false, false, true><<<dim3(MB, 2), 256, MMA_SMEM>>>(  // 6
        hA, nullptr, wh + 81920, wl + 81920, nullptr, hs, z);
    k_sdot<<<WB, 256>>>(a1);                                       // 7
    k_gat<false><<<WB, 256>>>(hA, hB, nullptr, nullptr, nullptr);  // 8

    // GAT layer 2 + fused output projection: hB -> out
    k_mma<H, false, false, true><<<dim3(MB, 2), 256, MMA_SMEM>>>(  // 9
        hB, nullptr, wh + 81920 + 32768, wl + 81920 + 32768, nullptr, hs, z);
    k_sdot<<<WB, 256>>>(a2);                                       // 10
    k_gat<true><<<WB, 256>>>(hB, nullptr, W_out, b_out, out);      // 11
}

// round 17
// speedup vs baseline: 1.0103x; 1.0021x over previous
#include <cuda_runtime.h>
#include <cuda_bf16.h>
#include <cstdint>

#define N_NODES 20000
#define E_EDGES 640000
#define IN_DIM  24
#define H       128
#define OUT_DIM 24
#define MAPD    512

typedef unsigned long long u64;

// ---------------- mma / ldmatrix helpers (baseline PTX, compute_103-safe) ----------------
__device__ __forceinline__ unsigned smem_u32(const void* p) {
    unsigned r;
    asm("{.reg .u64 t; cvta.to.shared.u64 t, %1; cvt.u32.u64 %0, t;}" : "=r"(r) : "l"(p));
    return r;
}
__device__ __forceinline__ void ldsm_x4(unsigned* r, unsigned addr) {
    asm volatile("ldmatrix.sync.aligned.m8n8.x4.shared.b16 {%0,%1,%2,%3}, [%4];"
                 : "=r"(r[0]), "=r"(r[1]), "=r"(r[2]), "=r"(r[3]) : "r"(addr));
}
__device__ __forceinline__ void mma16816(float* c, const unsigned* a, unsigned b0, unsigned b1) {
    asm volatile(
        "mma.sync.aligned.m16n8k16.row.col.f32.bf16.bf16.f32 "
        "{%0,%1,%2,%3}, {%4,%5,%6,%7}, {%8,%9}, {%0,%1,%2,%3};"
        : "+f"(c[0]), "+f"(c[1]), "+f"(c[2]), "+f"(c[3])
        : "r"(a[0]), "r"(a[1]), "r"(a[2]), "r"(a[3]), "r"(b0), "r"(b1));
}
__device__ __forceinline__ unsigned pack_bf2(float x, float y) {
    __nv_bfloat162 t = __floats2bfloat162_rn(x, y);
    return *(unsigned*)&t;
}

// ---------------- scratch ----------------
__device__ float g_hemb[N_NODES * H];
__device__ float g_hA[N_NODES * H];
__device__ float g_hB[N_NODES * H];
__device__ float g_hs[N_NODES * H];
__device__ float g_z[N_NODES * H];
__device__ float g_ssrc[N_NODES];
__device__ float g_sdst[N_NODES];
__device__ int   g_offs[N_NODES + 1];
__device__ int   g_cnt[N_NODES];
__device__ int   g_cur[N_NODES];
__device__ int   g_csrc[E_EDGES];
// pre-split weights: [Wcat 81920][Ws1 16384][Wf1 16384][Ws2 16384][Wf2 16384]
#define W_TOT (81920 + 4 * 16384)
__device__ __nv_bfloat16 g_Wh[W_TOT];
__device__ __nv_bfloat16 g_Wl[W_TOT];

// ---------------- CSR build ----------------
__global__ void k_zero() {
    int i = blockIdx.x * blockDim.x + threadIdx.x;
    if (i < N_NODES) { g_cnt[i] = 0; g_cur[i] = 0; }
}

__global__ void k_hist_embed(const int* __restrict__ dst,
                             const float* __restrict__ feats,
                             const float* __restrict__ W_eh,
                             const float* __restrict__ b_eh) {
    if (blockIdx.x < 2500) {
        int e = blockIdx.x * 256 + threadIdx.x;
        if (e < E_EDGES) atomicAdd(&g_cnt[dst[e]], 1);
        return;
    }
    int nb = blockIdx.x - 2500;
    __shared__ float f[2][IN_DIM];
    int half = threadIdx.x >> 7;
    int h = threadIdx.x & 127;
    int n = nb * 2 + half;
    if (h < IN_DIM) f[half][h] = feats[n * IN_DIM + h];
    __syncthreads();
    float acc = b_eh[h];
    #pragma unroll
    for (int k = 0; k < IN_DIM; k++) acc += f[half][k] * W_eh[h * IN_DIM + k];
    g_hemb[n * H + h] = acc;
}

__global__ void k_scan() {
    const int PER = 20;
    int t = threadIdx.x;
    int base = t * PER;
    int vals[PER];
    int s = 0;
    #pragma unroll
    for (int p = 0; p < PER; p++) {
        int i = base + p;
        int v = (i < N_NODES) ? g_cnt[i] : 0;
        vals[p] = s;
        s += v;
    }
    __shared__ int sh[1024];
    sh[t] = s;
    __syncthreads();
    #pragma unroll
    for (int off = 1; off < 1024; off <<= 1) {
        int x = (t >= off) ? sh[t - off] : 0;
        __syncthreads();
        sh[t] += x;
        __syncthreads();
    }
    int excl = sh[t] - s;
    #pragma unroll
    for (int p = 0; p < PER; p++) {
        int i = base + p;
        if (i < N_NODES) g_offs[i] = excl + vals[p];
    }
    if (t == 1023) g_offs[N_NODES] = sh[1023];
}

__global__ void k_scatter(const int* __restrict__ src, const int* __restrict__ dst) {
    int e = blockIdx.x * blockDim.x + threadIdx.x;
    if (e < E_EDGES) {
        int d = dst[e];
        int p = g_offs[d] + atomicAdd(&g_cur[d], 1);
        g_csrc[p] = src[e];
    }
}

// ---------------- weight split prep ----------------
__global__ void k_wsplit(const float* __restrict__ Wcat, const float* __restrict__ Ws1,
                         const float* __restrict__ Wf1, const float* __restrict__ Ws2,
                         const float* __restrict__ Wf2) {
    int i = blockIdx.x * 256 + threadIdx.x;
    if (i >= W_TOT) return;
    float v;
    if (i < 81920) v = Wcat[i];
    else {
        int j = i - 81920;
        int m = j >> 14, o = j & 16383;
        v = (m == 0 ? Ws1 : (m == 1 ? Wf1 : (m == 2 ? Ws2 : Wf2)))[o];
    }
    __nv_bfloat16 h = __float2bfloat16(v);
    __nv_bfloat16 l = __float2bfloat16(v - __bfloat162float(h));
    g_Wh[i] = h;
    g_Wl[i] = l;
}

// ---------------- HMMA bf16x3-split GEMM ----------------
// C[row0:row0+128, 0:128] = X @ W[128,KDIM]^T (+bias+relu)
// 8 warps: wm = wid&3 (32 rows), wn = wid>>2 (64 cols)
// smem: AH/AL [128][64] bf16 (16KB each), BH/BL [128][64] bf16 (16KB each) = 64KB
template <int KDIM, bool CONCAT, bool BIASRELU, bool DUAL>
__global__ void __launch_bounds__(256)
k_mma(const float* __restrict__ A0, const float* __restrict__ A1,
      const __nv_bfloat16* __restrict__ WhB, const __nv_bfloat16* __restrict__ WlB,
      const float* __restrict__ bias,
      float* __restrict__ C0, float* __restrict__ C1) {
    extern __shared__ char sm[];
    const unsigned OFF_AH = 0, OFF_AL = 16384, OFF_BH = 32768, OFF_BL = 49152;
    unsigned sb = smem_u32(sm);

    int tid = threadIdx.x, lane = tid & 31, wid = tid >> 5;
    int wm = wid & 3, wn = wid >> 2;
    int y = DUAL ? blockIdx.y : 0;
    const __nv_bfloat16* Wh = WhB + (DUAL ? y * (128 * KDIM) : 0);
    const __nv_bfloat16* Wl = WlB + (DUAL ? y * (128 * KDIM) : 0);
    float* C = DUAL ? (y ? C1 : C0) : C0;
    int row0 = blockIdx.x * 128;

    float acc[2][8][4];
    #pragma unroll
    for (int i = 0; i < 2; i++)
        #pragma unroll
        for (int j = 0; j < 8; j++)
            #pragma unroll
            for (int q = 0; q < 4; q++) acc[i][j][q] = 0.f;

    // ldmatrix address precompute
    // A: matrix layout: khalf = lane>>4, rowhalf = (lane>>3)&1, r8 = lane&7
    int a_rh = (lane >> 3) & 1, a_kh = lane >> 4, r8 = lane & 7;
    int rowA[2], xorA[2];
    #pragma unroll
    for (int mt = 0; mt < 2; mt++) {
        rowA[mt] = wm * 32 + mt * 16 + a_rh * 8 + r8;
        xorA[mt] = rowA[mt] & 7;
    }
    // B: nhalf = (lane>>4)&1, khalf = (lane>>3)&1
    int b_nh = (lane >> 4) & 1, b_kh = (lane >> 3) & 1;
    int rowB[4], xorB[4];
    #pragma unroll
    for (int nt2 = 0; nt2 < 4; nt2++) {
        rowB[nt2] = wn * 64 + nt2 * 16 + b_nh * 8 + r8;
        xorB[nt2] = rowB[nt2] & 7;
    }

    const int NT = KDIM / 64;
    for (int kt = 0; kt < NT; kt++) {
        int k0 = kt * 64;
        // --- A tile: 128x64 fp32 -> hi/lo bf16, swizzled ---
        #pragma unroll
        for (int p = 0; p < 8; p++) {
            int idx = tid + p * 256;
            int row = idx >> 4, c4 = idx & 15;
            int grow = row0 + row, gk = k0 + c4 * 4;
            float4 v = make_float4(0.f, 0.f, 0.f, 0.f);
            if (grow < N_NODES) {
                if (CONCAT) v = (gk < MAPD) ? *(const float4*)&A0[grow * MAPD + gk]
                                            : *(const float4*)&A1[grow * H + (gk - MAPD)];
                else        v = *(const float4*)&A0[grow * KDIM + gk];
            }
            unsigned h0 = pack_bf2(v.x, v.y), h1 = pack_bf2(v.z, v.w);
            float rx = v.x - __bfloat162float(__float2bfloat16(v.x));
            float ry = v.y - __bfloat162float(__float2bfloat16(v.y));
            float rz = v.z - __bfloat162float(__float2bfloat16(v.z));
            float rw = v.w - __bfloat162float(__float2bfloat16(v.w));
            unsigned l0 = pack_bf2(rx, ry), l1 = pack_bf2(rz, rw);
            unsigned off = row * 128 + c4 * 8;
            unsigned sw = off ^ ((row & 7) << 4);
            *(uint2*)(sm + OFF_AH + sw) = make_uint2(h0, h1);
            *(uint2*)(sm + OFF_AL + sw) = make_uint2(l0, l1);
        }
        // --- B tile: 128x64 bf16 hi/lo (pre-split), swizzled ---
        #pragma unroll
        for (int p = 0; p < 4; p++) {
            int idx = tid + p * 256;
            int row = idx >> 3, c16 = idx & 7;
            unsigned off = row * 128 + c16 * 16;
            unsigned sw = off ^ ((row & 7) << 4);
            const __nv_bfloat16* gh = &Wh[row * KDIM + k0 + c16 * 8];
            const __nv_bfloat16* gl = &Wl[row * KDIM + k0 + c16 * 8];
            *(uint4*)(sm + OFF_BH + sw) = *(const uint4*)gh;
            *(uint4*)(sm + OFF_BL + sw) = *(const uint4*)gl;
        }
        __syncthreads();

        #pragma unroll
        for (int ks = 0; ks < 4; ks++) {
            unsigned ah[2][4], al[2][4];
            #pragma unroll
            for (int mt = 0; mt < 2; mt++) {
                unsigned chunk = (ks * 2 + a_kh) ^ xorA[mt];
                unsigned o = rowA[mt] * 128 + chunk * 16;
                ldsm_x4(ah[mt], sb + OFF_AH + o);
                ldsm_x4(al[mt], sb + OFF_AL + o);
            }
            unsigned bh[4][4], bl[4][4];
            #pragma unroll
            for (int nt2 = 0; nt2 < 4; nt2++) {
                unsigned chunk = (ks * 2 + b_kh) ^ xorB[nt2];
                unsigned o = rowB[nt2] * 128 + chunk * 16;
                ldsm_x4(bh[nt2], sb + OFF_BH + o);
                ldsm_x4(bl[nt2], sb + OFF_BL + o);
            }
            #pragma unroll
            for (int mt = 0; mt < 2; mt++)
                #pragma unroll
                for (int nt = 0; nt < 8; nt++) {
                    float* c = acc[mt][nt];
                    unsigned s = (nt & 1) * 2;
                    const unsigned* BH_ = bh[nt >> 1];
                    const unsigned* BL_ = bl[nt >> 1];
                    mma16816(c, ah[mt], BH_[s], BH_[s + 1]);
                    mma16816(c, ah[mt], BL_[s], BL_[s + 1]);
                    mma16816(c, al[mt], BH_[s], BH_[s + 1]);
                }
        }
        __syncthreads();
    }

    // --- epilogue ---
    int cbase = wn * 64 + (lane & 3) * 2;
    int rbase = row0 + wm * 32 + (lane >> 2);
    #pragma unroll
    for (int mt = 0; mt < 2; mt++) {
        #pragma unroll
        for (int nt = 0; nt < 8; nt++) {
            int col = cbase + nt * 8;
            float b0 = 0.f, b1 = 0.f;
            if (BIASRELU) { b0 = bias[col]; b1 = bias[col + 1]; }
            int r0 = rbase + mt * 16;
            int r1 = r0 + 8;
            float* c = acc[mt][nt];
            if (r0 < N_NODES) {
                float2 v = make_float2(c[0] + b0, c[1] + b1);
                if (BIASRELU) { v.x = fmaxf(v.x, 0.f); v.y = fmaxf(v.y, 0.f); }
                *(float2*)&C[r0 * H + col] = v;
            }
            if (r1 < N_NODES) {
                float2 v = make_float2(c[2] + b0, c[3] + b1);
                if (BIASRELU) { v.x = fmaxf(v.x, 0.f); v.y = fmaxf(v.y, 0.f); }
                *(float2*)&C[r1 * H + col] = v;
            }
        }
    }
}
#define MMA_SMEM 65536

// ---------------- per-node attention halves ----------------
__global__ void k_sdot(const float* __restrict__ a) {
    int warp = (blockIdx.x * blockDim.x + threadIdx.x) >> 5;
    int lane = threadIdx.x & 31;
    if (warp >= N_NODES) return;
    float4 zv = *(const float4*)&g_z[warp * H + lane * 4];
    float4 a0 = *(const float4*)&a[lane * 4];
    float4 a1 = *(const float4*)&a[H + lane * 4];
    float s0 = zv.x * a0.x + zv.y * a0.y + zv.z * a0.z + zv.w * a0.w;
    float s1 = zv.x * a1.x + zv.y * a1.y + zv.z * a1.z + zv.w * a1.w;
    #pragma unroll
    for (int off = 16; off; off >>= 1) {
        s0 += __shfl_xor_sync(0xffffffffu, s0, off);
        s1 += __shfl_xor_sync(0xffffffffu, s1, off);
    }
    if (lane == 0) { g_ssrc[warp] = s0; g_sdst[warp] = s1; }
}

// ---------------- fused GAT edge kernel (warp/node); optional out-proj epilogue ----------------
template <bool DO_OUT>
__global__ void k_gat(const float* __restrict__ hin, float* __restrict__ hout,
                      const float* __restrict__ Wout, const float* __restrict__ bout,
                      float* __restrict__ out) {
    __shared__ float ws[DO_OUT ? OUT_DIM * H : 1];
    __shared__ float bs[DO_OUT ? OUT_DIM : 1];
    if (DO_OUT) {
        for (int i = threadIdx.x; i < OUT_DIM * H; i += blockDim.x) ws[i] = Wout[i];
        if (threadIdx.x < OUT_DIM) bs[threadIdx.x] = bout[threadIdx.x];
        __syncthreads();
    }
    int node = blockIdx.x * (blockDim.x >> 5) + (threadIdx.x >> 5);
    int lane = threadIdx.x & 31;
    if (node >= N_NODES) return;
    int beg = g_offs[node], end = g_offs[node + 1];
    float4 hi = *(const float4*)&hin[node * H + lane * 4];
    float4 o4;
    if (beg == end) {
        o4 = make_float4(2.f * hi.x, 2.f * hi.y, 2.f * hi.z, 2.f * hi.w);
    } else {
        float sd = g_sdst[node];
        float mx = -3.0e38f;
        for (int j = beg + lane; j < end; j += 32) {
            float x = g_ssrc[g_csrc[j]] + sd;
            mx = fmaxf(mx, fmaxf(x, 0.01f * x));
        }
        #pragma unroll
        for (int off = 16; off; off >>= 1) mx = fmaxf(mx, __shfl_xor_sync(0xffffffffu, mx, off));
        float den = 0.f;
        for (int j = beg + lane; j < end; j += 32) {
            float x = g_ssrc[g_csrc[j]] + sd;
            den += __expf(fmaxf(x, 0.01f * x) - mx);
        }
        #pragma unroll
        for (int off = 16; off; off >>= 1) den += __shfl_xor_sync(0xffffffffu, den, off);
        float invden = 1.f / fmaxf(den, 1e-16f);
        float4 acc = make_float4(0.f, 0.f, 0.f, 0.f);
        for (int base = beg; base < end; base += 32) {
            int j = base + lane;
            float coeff = 0.f; int s = 0;
            if (j < end) {
                s = g_csrc[j];
                float x = g_ssrc[s] + sd;
                coeff = __expf(fmaxf(x, 0.01f * x) - mx) * invden;
            }
            int cnt = min(32, end - base);
            if (cnt == 32) {
                #pragma unroll 8
                for (int t = 0; t < 32; t++) {
                    float c = __shfl_sync(0xffffffffu, coeff, t);
                    int ss = __shfl_sync(0xffffffffu, s, t);
                    float4 zv = *(const float4*)&g_z[ss * H + lane * 4];
                    acc.x += c * zv.x; acc.y += c * zv.y;
                    acc.z += c * zv.z; acc.w += c * zv.w;
                }
            } else {
                for (int t = 0; t < cnt; t++) {
                    float c = __shfl_sync(0xffffffffu, coeff, t);
                    int ss = __shfl_sync(0xffffffffu, s, t);
                    float4 zv = *(const float4*)&g_z[ss * H + lane * 4];
                    acc.x += c * zv.x; acc.y += c * zv.y;
                    acc.z += c * zv.z; acc.w += c * zv.w;
                }
            }
        }
        float4 hs = *(const float4*)&g_hs[node * H + lane * 4];
        o4 = make_float4(hi.x + hs.x + acc.x, hi.y + hs.y + acc.y,
                         hi.z + hs.z + acc.z, hi.w + hs.w + acc.w);
    }
    if (!DO_OUT) {
        *(float4*)&hout[node * H + lane * 4] = o4;
    } else {
        float vout = 0.f;
        #pragma unroll
        for (int o = 0; o < OUT_DIM; o++) {
            float4 wv = *(const float4*)&ws[o * H + lane * 4];
            float p = o4.x * wv.x + o4.y * wv.y + o4.z * wv.z + o4.w * wv.w;
            #pragma unroll
            for (int off = 16; off; off >>= 1) p += __shfl_xor_sync(0xffffffffu, p, off);
            if (lane == o) vout = p + bs[o];
        }
        if (lane < OUT_DIM) out[node * OUT_DIM + lane] = vout;
    }
}

// ---------------- launch ----------------
extern "C" void kernel_launch(void* const* d_in, const int* in_sizes, int n_in,
                              void* d_out, int out_size) {
    const float* feats = (const float*)d_in[0];
    const float* maps  = (const float*)d_in[2];
    const int*   src   = (const int*)d_in[4];
    const int*   dst   = (const int*)d_in[5];
    const float* W_eh  = (const float*)d_in[6];
    const float* b_eh  = (const float*)d_in[7];
    const float* W_cat = (const float*)d_in[10];
    const float* b_cat = (const float*)d_in[11];
    const float* Ws1   = (const float*)d_in[12];
    const float* Wf1   = (const float*)d_in[13];
    const float* a1    = (const float*)d_in[14];
    const float* Ws2   = (const float*)d_in[15];
    const float* Wf2   = (const float*)d_in[16];
    const float* a2    = (const float*)d_in[17];
    const float* W_out = (const float*)d_in[18];
    const float* b_out = (const float*)d_in[19];
    float* out = (float*)d_out;

    float *hemb, *hA, *hB, *hs, *z;
    cudaGetSymbolAddress((void**)&hemb, g_hemb);
    cudaGetSymbolAddress((void**)&hA, g_hA);
    cudaGetSymbolAddress((void**)&hB, g_hB);
    cudaGetSymbolAddress((void**)&hs, g_hs);
    cudaGetSymbolAddress((void**)&z,  g_z);
    __nv_bfloat16 *wh, *wl;
    cudaGetSymbolAddress((void**)&wh, g_Wh);
    cudaGetSymbolAddress((void**)&wl, g_Wl);

    cudaFuncSetAttribute(k_mma<MAPD + H, true, true, false>,
                         cudaFuncAttributeMaxDynamicSharedMemorySize, MMA_SMEM);
    cudaFuncSetAttribute(k_mma<H, false, false, true>,
                         cudaFuncAttributeMaxDynamicSharedMemorySize, MMA_SMEM);

    const int MB = (N_NODES + 127) / 128; // 157
    const int EB = (E_EDGES + 255) / 256; // 2500
    const int WB = (N_NODES + 7) / 8;     // 2500

    k_zero<<<(N_NODES + 255) / 256, 256>>>();                      // 0
    k_hist_embed<<<EB + 10000, 256>>>(dst, feats, W_eh, b_eh);     // 1
    k_wsplit<<<(W_TOT + 255) / 256, 256>>>(W_cat, Ws1, Wf1, Ws2, Wf2); // 2
    // concat projection (HMMA) at profiled slot #3
    k_mma<MAPD + H, true, true, false><<<MB, 256, MMA_SMEM>>>(     // 3
        maps, hemb, wh, wl, b_cat, hA, nullptr);
    k_scan<<<1, 1024>>>();                                         // 4
    k_scatter<<<EB, 256>>>(src, dst);                              // 5

    // GAT layer 1: hA -> hB
    k_mma<H, false, false, true><<<dim3(MB, 2), 256, MMA_SMEM>>>(  // 6
        hA, nullptr, wh + 81920, wl + 81920, nullptr, hs, z);
    k_sdot<<<WB, 256>>>(a1);                                       // 7
    k_gat<false><<<WB, 256>>>(hA, hB, nullptr, nullptr, nullptr);  // 8

    // GAT layer 2 + fused output projection: hB -> out
    k_mma<H, false, false, true><<<dim3(MB, 2), 256, MMA_SMEM>>>(  // 9
        hB, nullptr, wh + 81920 + 32768, wl + 81920 + 32768, nullptr, hs, z);
    k_sdot<<<WB, 256>>>(a2);                                       // 10
    k_gat<true><<<WB, 256>>>(hB, nullptr, W_out, b_out, out);      // 11
}